// round 5
// baseline (speedup 1.0000x reference)
#include <cuda_runtime.h>
#include <math.h>

// Problem constants (fixed shapes)
#define Bn  8
#define Cn  32
#define Tn  4096
#define Kn  9
#define COn 32
#define Mc  12       // candidates per key-half
#define NH  2        // key halves
#define McT (Mc*NH)  // total candidates per query

// Scratch (no allocations allowed in kernel_launch)
__device__ double g_xn64[Bn * Tn * Cn];   // f64 normalized, token-major
__device__ float  g_xn32[Bn * Tn * Cn];   // f32 rounding of g_xn64
__device__ float  g_xf[Bn * Tn * Cn];     // raw features f32, token-major
__device__ float  g_wT[Cn * Kn * COn];    // weight transposed [(c*9+k)*32+o]
__device__ int    g_cand[Bn * Tn * McT];  // candidate indices (12 per half)
__device__ float  g_vals[Bn * Tn * Kn];   // final top-K vals (sorted desc)
__device__ int    g_idx[Bn * Tn * Kn];    // final top-K indices

// ---------------------------------------------------------------------------
// Kernel 1: f64 per-token L2 norm + normalize.
// ---------------------------------------------------------------------------
__global__ __launch_bounds__(256) void prep_kernel(const float* __restrict__ x) {
    int b = blockIdx.y;
    int t = blockIdx.x * 256 + threadIdx.x;
    const float* xb = x + (size_t)b * Cn * Tn;

    float v[Cn];
    double ss = 0.0;
#pragma unroll
    for (int c = 0; c < Cn; c++) {
        float f = xb[(size_t)c * Tn + t];
        v[c] = f;
        ss = fma((double)f, (double)f, ss);
    }
    double rin = 1.0 / fmax(sqrt(ss), 1e-12);

    size_t base = ((size_t)b * Tn + t) * Cn;
    double* p64 = g_xn64 + base;
    float4* pf = reinterpret_cast<float4*>(g_xf + base);
    float4* pn = reinterpret_cast<float4*>(g_xn32 + base);
#pragma unroll
    for (int c = 0; c < Cn; c += 4) {
        double d0 = (double)v[c] * rin, d1 = (double)v[c + 1] * rin;
        double d2 = (double)v[c + 2] * rin, d3 = (double)v[c + 3] * rin;
        p64[c] = d0; p64[c + 1] = d1; p64[c + 2] = d2; p64[c + 3] = d3;
        pf[c / 4] = make_float4(v[c], v[c + 1], v[c + 2], v[c + 3]);
        pn[c / 4] = make_float4((float)d0, (float)d1, (float)d2, (float)d3);
    }
}

// ---------------------------------------------------------------------------
// Kernel 1b: transpose conv weight to [(c*9+k)*32 + o].
// ---------------------------------------------------------------------------
__global__ void wt_kernel(const float* __restrict__ w) {
    int i = blockIdx.x * 256 + threadIdx.x;
    if (i < COn * Cn * Kn) {
        int o = i / (Cn * Kn);
        int rem = i % (Cn * Kn);
        int c = rem / Kn;
        int k = rem % Kn;
        g_wT[(c * Kn + k) * COn + o] = w[i];
    }
}

// ---------------------------------------------------------------------------
// Kernel 2: fp32 similarity fast pass. Each thread owns TWO queries; each
// block scans HALF the keys (2048) and emits top-12 candidates per query
// for its half. 8 LDS.128 per key feed 128 FFMA (2 queries x 2 keys x 32c)
// -> LSU and FFMA pipes balanced and overlapped. Halves are disjoint, so
// the 24-candidate union provably contains the exact top-9.
// ---------------------------------------------------------------------------
#define TKEY 128
#define QBLK 256   // queries per block (128 threads x 2)

#define INSERT(list_v, list_i, sval, sidx)                                   \
    if ((sval) > list_v[Mc - 1]) {                                           \
        list_v[Mc - 1] = (sval); list_i[Mc - 1] = (sidx);                    \
        _Pragma("unroll")                                                    \
        for (int pp = Mc - 1; pp > 0; --pp) {                                \
            if (list_v[pp] > list_v[pp - 1]) {                               \
                float tv = list_v[pp]; list_v[pp] = list_v[pp - 1];          \
                list_v[pp - 1] = tv;                                         \
                int ti = list_i[pp]; list_i[pp] = list_i[pp - 1];            \
                list_i[pp - 1] = ti;                                         \
            }                                                                \
        }                                                                    \
    }

__global__ __launch_bounds__(128) void topk_kernel() {
    int b  = blockIdx.y;
    int qb = blockIdx.x >> 1;        // query block
    int kh = blockIdx.x & 1;         // key half
    int q0 = qb * QBLK + threadIdx.x;
    int q1 = q0 + 128;
    const float* xnb = g_xn32 + (size_t)b * Tn * Cn;

    float4 qA[Cn / 4], qB[Cn / 4];
    {
        const float4* p0 = reinterpret_cast<const float4*>(xnb + (size_t)q0 * Cn);
        const float4* p1 = reinterpret_cast<const float4*>(xnb + (size_t)q1 * Cn);
#pragma unroll
        for (int c4 = 0; c4 < Cn / 4; c4++) { qA[c4] = p0[c4]; qB[c4] = p1[c4]; }
    }

    float vA[Mc], vB[Mc];
    int   iA[Mc], iB[Mc];
#pragma unroll
    for (int p = 0; p < Mc; p++) { vA[p] = -2.f; iA[p] = 0; vB[p] = -2.f; iB[p] = 0; }

    __shared__ float4 ks[TKEY][Cn / 4];   // 16 KB

    int kbeg = kh * (Tn / NH);
    int kend = kbeg + (Tn / NH);

    for (int tile = kbeg; tile < kend; tile += TKEY) {
        __syncthreads();
        const float4* src = reinterpret_cast<const float4*>(xnb + (size_t)tile * Cn);
#pragma unroll
        for (int i = threadIdx.x; i < TKEY * (Cn / 4); i += 128) {
            (&ks[0][0])[i] = src[i];
        }
        __syncthreads();

#pragma unroll 2
        for (int j = 0; j < TKEY; j += 2) {
            const float4* r0 = &ks[j][0];
            const float4* r1 = &ks[j + 1][0];
            float a00 = 0.f, a01 = 0.f, a10 = 0.f, a11 = 0.f;
#pragma unroll
            for (int c4 = 0; c4 < Cn / 4; c4++) {
                float4 k0 = r0[c4];
                float4 k1 = r1[c4];
                float4 fa = qA[c4];
                float4 fb = qB[c4];
                a00 = fmaf(fa.x, k0.x, a00); a00 = fmaf(fa.y, k0.y, a00);
                a00 = fmaf(fa.z, k0.z, a00); a00 = fmaf(fa.w, k0.w, a00);
                a01 = fmaf(fa.x, k1.x, a01); a01 = fmaf(fa.y, k1.y, a01);
                a01 = fmaf(fa.z, k1.z, a01); a01 = fmaf(fa.w, k1.w, a01);
                a10 = fmaf(fb.x, k0.x, a10); a10 = fmaf(fb.y, k0.y, a10);
                a10 = fmaf(fb.z, k0.z, a10); a10 = fmaf(fb.w, k0.w, a10);
                a11 = fmaf(fb.x, k1.x, a11); a11 = fmaf(fb.y, k1.y, a11);
                a11 = fmaf(fb.z, k1.z, a11); a11 = fmaf(fb.w, k1.w, a11);
            }
            INSERT(vA, iA, a00, tile + j)
            INSERT(vA, iA, a01, tile + j + 1)
            INSERT(vB, iB, a10, tile + j)
            INSERT(vB, iB, a11, tile + j + 1)
        }
    }

    size_t oA = ((size_t)b * Tn + q0) * McT + kh * Mc;
    size_t oB = ((size_t)b * Tn + q1) * McT + kh * Mc;
#pragma unroll
    for (int p = 0; p < Mc; p++) {
        g_cand[oA + p] = iA[p];
        g_cand[oB + p] = iB[p];
    }
}

// ---------------------------------------------------------------------------
// Kernel 3: exact f64 rescore. One WARP per query; lane m < 24 rescored
// candidate m with a sequential DFMA chain (query broadcast via shfl).
// Rank by (value desc, index asc) via all-pairs comparison -> exact
// jax.lax.top_k semantics. Candidate halves are disjoint -> ranks unique.
// ---------------------------------------------------------------------------
__global__ __launch_bounds__(256) void rescore_kernel() {
    int warp = threadIdx.x >> 5;
    int lane = threadIdx.x & 31;
    int qg = blockIdx.x * 8 + warp;          // global query id in [0, Bn*Tn)
    int b = qg >> 12;                        // /Tn
    int q = qg & (Tn - 1);
    const double* xnb = g_xn64 + (size_t)b * Tn * Cn;

    // lane l caches q[l] (coalesced); broadcast per-c via shfl
    double qd = xnb[(size_t)q * Cn + lane];

    size_t cbase = (size_t)qg * McT;
    int ii = (lane < McT) ? g_cand[cbase + lane] : 0;
    const double* xs = xnb + (size_t)ii * Cn;

    double acc = 0.0;
#pragma unroll
    for (int c = 0; c < Cn; c++) {
        double qc = __shfl_sync(0xffffffffu, qd, c);
        acc = fma(qc, xs[c], acc);
    }
    double s = fmin(fmax(acc, -1.0), 1.0);

    // all-pairs rank among the 24 candidates
    int rank = 0;
#pragma unroll
    for (int j = 0; j < McT; j++) {
        double vj = __shfl_sync(0xffffffffu, s, j);
        int    ij = __shfl_sync(0xffffffffu, ii, j);
        bool better = (vj > s) || (vj == s && ij < ii);
        if (lane < McT && j != lane && better) rank++;
    }

    if (lane < McT && rank < Kn) {
        size_t obase = (size_t)qg * Kn;
        g_vals[obase + rank] = (float)s;
        g_idx[obase + rank]  = ii;
    }
}

// ---------------------------------------------------------------------------
// Kernel 4: gather + conv. Warp handles 4 tokens; weight read once per
// (c,k) from L1-resident transposed global, reused across the 4 tokens.
// ---------------------------------------------------------------------------
__global__ __launch_bounds__(256) void conv_kernel(const float* __restrict__ bias,
                                                   float* __restrict__ out) {
    __shared__ float prime[8][4][Kn][Cn];

    int b = blockIdx.y;
    int warp = threadIdx.x >> 5;
    int lane = threadIdx.x & 31;
    const float* xfb = g_xf + (size_t)b * Tn * Cn;

    int t0 = blockIdx.x * 32 + warp * 4;
    size_t vbase = ((size_t)b * Tn + t0) * Kn;

#pragma unroll
    for (int m = 0; m < 4 * Kn; m++) {
        int tt = m / Kn, k = m % Kn;
        float vk = g_vals[vbase + tt * Kn + k];
        int   ik = g_idx[vbase + tt * Kn + k];
        prime[warp][tt][k][lane] = vk * xfb[(size_t)ik * Cn + lane];
    }
    __syncwarp();

    float bsl = bias[lane];
    float a0 = bsl, a1 = bsl, a2 = bsl, a3 = bsl;
#pragma unroll
    for (int c = 0; c < Cn; c++) {
#pragma unroll
        for (int k = 0; k < Kn; k++) {
            float wv = g_wT[(c * Kn + k) * COn + lane];
            a0 = fmaf(prime[warp][0][k][c], wv, a0);
            a1 = fmaf(prime[warp][1][k][c], wv, a1);
            a2 = fmaf(prime[warp][2][k][c], wv, a2);
            a3 = fmaf(prime[warp][3][k][c], wv, a3);
        }
    }
    size_t ob = ((size_t)b * COn + lane) * Tn + t0;
    out[ob + 0] = a0; out[ob + 1] = a1; out[ob + 2] = a2; out[ob + 3] = a3;
}

// ---------------------------------------------------------------------------
extern "C" void kernel_launch(void* const* d_in, const int* in_sizes, int n_in,
                              void* d_out, int out_size) {
    const float* x    = (const float*)d_in[0];  // [8,32,64,64]
    const float* w    = (const float*)d_in[1];  // [32,32,9]
    const float* bias = (const float*)d_in[2];  // [32]
    float* out = (float*)d_out;                 // [8,32,64,64]

    prep_kernel<<<dim3(Tn / 256, Bn), 256>>>(x);
    wt_kernel<<<(COn * Cn * Kn + 255) / 256, 256>>>(w);
    topk_kernel<<<dim3((Tn / QBLK) * NH, Bn), 128>>>();
    rescore_kernel<<<(Bn * Tn) / 8, 256>>>();
    conv_kernel<<<dim3(Tn / 32, Bn), 256>>>(bias, out);
}

// round 6
// speedup vs baseline: 1.2699x; 1.2699x over previous
#include <cuda_runtime.h>
#include <math.h>

// Problem constants (fixed shapes)
#define Bn  8
#define Cn  32
#define Tn  4096
#define Kn  9
#define COn 32
#define Mc  12       // candidates per key-half
#define NH  2        // key halves
#define McT (Mc*NH)  // total candidates per query

// Scratch (no allocations allowed in kernel_launch)
__device__ float  g_xn32[Bn * Tn * Cn];   // fast-pass normalized f32, token-major
__device__ float  g_xf[Bn * Tn * Cn];     // raw features f32, token-major
__device__ double g_rinv[Bn * Tn];        // f64 1/norm per token
__device__ float  g_wT[Cn * Kn * COn];    // weight transposed [(c*9+k)*32+o]
__device__ int    g_cand[Bn * Tn * McT];  // candidate indices (12 per half)
__device__ float  g_vals[Bn * Tn * Kn];   // final top-K vals (sorted desc)
__device__ int    g_idx[Bn * Tn * Kn];    // final top-K indices

// ---------------------------------------------------------------------------
// Kernel 1: per-token transpose + f64 norm reciprocal + f32 normalized copy.
// ---------------------------------------------------------------------------
__global__ __launch_bounds__(256) void prep_kernel(const float* __restrict__ x) {
    int b = blockIdx.y;
    int t = blockIdx.x * 256 + threadIdx.x;
    const float* xb = x + (size_t)b * Cn * Tn;

    float v[Cn];
    double ss = 0.0;
#pragma unroll
    for (int c = 0; c < Cn; c++) {
        float f = xb[(size_t)c * Tn + t];
        v[c] = f;
        ss = fma((double)f, (double)f, ss);
    }
    double rin = 1.0 / fmax(sqrt(ss), 1e-12);
    g_rinv[(size_t)b * Tn + t] = rin;

    size_t base = ((size_t)b * Tn + t) * Cn;
    float4* pf = reinterpret_cast<float4*>(g_xf + base);
    float4* pn = reinterpret_cast<float4*>(g_xn32 + base);
#pragma unroll
    for (int c = 0; c < Cn; c += 4) {
        pf[c / 4] = make_float4(v[c], v[c + 1], v[c + 2], v[c + 3]);
        pn[c / 4] = make_float4((float)((double)v[c] * rin),
                                (float)((double)v[c + 1] * rin),
                                (float)((double)v[c + 2] * rin),
                                (float)((double)v[c + 3] * rin));
    }
}

// ---------------------------------------------------------------------------
// Kernel 1b: transpose conv weight to [(c*9+k)*32 + o].
// ---------------------------------------------------------------------------
__global__ void wt_kernel(const float* __restrict__ w) {
    int i = blockIdx.x * 256 + threadIdx.x;
    if (i < COn * Cn * Kn) {
        int o = i / (Cn * Kn);
        int rem = i % (Cn * Kn);
        int c = rem / Kn;
        int k = rem % Kn;
        g_wT[(c * Kn + k) * COn + o] = w[i];
    }
}

// ---------------------------------------------------------------------------
// Kernel 2: fp32 similarity fast pass. 256 threads/block, 1 query/thread,
// each block scans one key HALF (2048 keys) -> 65536 threads, ~3.5
// warps/SMSP to keep the FFMA pipe fed. Keys broadcast from smem tiles.
// Halves are disjoint, so the 24-candidate union contains the true top-9.
// ---------------------------------------------------------------------------
#define TKEY 128
#define QBLK 256   // queries per block (1 per thread)

#define INSERT(list_v, list_i, sval, sidx)                                   \
    if ((sval) > list_v[Mc - 1]) {                                           \
        list_v[Mc - 1] = (sval); list_i[Mc - 1] = (sidx);                    \
        _Pragma("unroll")                                                    \
        for (int pp = Mc - 1; pp > 0; --pp) {                                \
            if (list_v[pp] > list_v[pp - 1]) {                               \
                float tv = list_v[pp]; list_v[pp] = list_v[pp - 1];          \
                list_v[pp - 1] = tv;                                         \
                int ti = list_i[pp]; list_i[pp] = list_i[pp - 1];            \
                list_i[pp - 1] = ti;                                         \
            }                                                                \
        }                                                                    \
    }

__global__ __launch_bounds__(256) void topk_kernel() {
    int b  = blockIdx.y;
    int qb = blockIdx.x >> 1;        // query block
    int kh = blockIdx.x & 1;         // key half
    int q  = qb * QBLK + threadIdx.x;
    const float* xnb = g_xn32 + (size_t)b * Tn * Cn;

    float4 qv[Cn / 4];
    {
        const float4* qp = reinterpret_cast<const float4*>(xnb + (size_t)q * Cn);
#pragma unroll
        for (int c4 = 0; c4 < Cn / 4; c4++) qv[c4] = qp[c4];
    }

    float v[Mc];
    int   id[Mc];
#pragma unroll
    for (int p = 0; p < Mc; p++) { v[p] = -2.f; id[p] = 0; }

    __shared__ float4 ks[TKEY][Cn / 4];   // 16 KB

    int kbeg = kh * (Tn / NH);
    int kend = kbeg + (Tn / NH);

    for (int tile = kbeg; tile < kend; tile += TKEY) {
        __syncthreads();
        const float4* src = reinterpret_cast<const float4*>(xnb + (size_t)tile * Cn);
#pragma unroll
        for (int i = threadIdx.x; i < TKEY * (Cn / 4); i += 256) {
            (&ks[0][0])[i] = src[i];
        }
        __syncthreads();

#pragma unroll 2
        for (int j = 0; j < TKEY; j += 2) {
            const float4* r0 = &ks[j][0];
            const float4* r1 = &ks[j + 1][0];
            float s0a = 0.f, s0b = 0.f, s1a = 0.f, s1b = 0.f;
#pragma unroll
            for (int c4 = 0; c4 < Cn / 4; c4++) {
                float4 k0 = r0[c4];
                float4 k1 = r1[c4];
                float4 qq = qv[c4];
                s0a = fmaf(qq.x, k0.x, s0a); s0b = fmaf(qq.y, k0.y, s0b);
                s1a = fmaf(qq.x, k1.x, s1a); s1b = fmaf(qq.y, k1.y, s1b);
                s0a = fmaf(qq.z, k0.z, s0a); s0b = fmaf(qq.w, k0.w, s0b);
                s1a = fmaf(qq.z, k1.z, s1a); s1b = fmaf(qq.w, k1.w, s1b);
            }
            float s0 = s0a + s0b;
            float s1 = s1a + s1b;
            INSERT(v, id, s0, tile + j)
            INSERT(v, id, s1, tile + j + 1)
        }
    }

    size_t obase = ((size_t)b * Tn + q) * McT + kh * Mc;
#pragma unroll
    for (int p = 0; p < Mc; p++) g_cand[obase + p] = id[p];
}

// ---------------------------------------------------------------------------
// Kernel 3: rank-exact rescore, thread-per-query. Compensated fp32 dot
// (Ogita-Rump Dot2: TwoProdFMA + TwoSum, rigorous error ~u^2*cond ~1e-14)
// over RAW f32 rows, combined with f64 norm reciprocals. Running sorted
// top-9 with (value desc, index asc) comparator == jax.lax.top_k.
// ---------------------------------------------------------------------------
__global__ __launch_bounds__(128) void rescore_kernel() {
    int qg = blockIdx.x * 128 + threadIdx.x;   // global query id
    int b = qg >> 12;
    int q = qg & (Tn - 1);
    const float* xfb = g_xf + (size_t)b * Tn * Cn;
    const double* rinvb = g_rinv + (size_t)b * Tn;

    float qv[Cn];
    {
        const float4* qp = reinterpret_cast<const float4*>(xfb + (size_t)q * Cn);
#pragma unroll
        for (int c4 = 0; c4 < Cn / 4; c4++) {
            float4 f = qp[c4];
            qv[4 * c4] = f.x; qv[4 * c4 + 1] = f.y;
            qv[4 * c4 + 2] = f.z; qv[4 * c4 + 3] = f.w;
        }
    }
    double rq = rinvb[q];

    double bv[Kn];
    int    bi[Kn];
#pragma unroll
    for (int p = 0; p < Kn; p++) { bv[p] = -3.0; bi[p] = 0x7fffffff; }

    size_t cbase = (size_t)qg * McT;
#pragma unroll 1
    for (int m = 0; m < McT; m++) {
        int ii = g_cand[cbase + m];
        const float4* xs = reinterpret_cast<const float4*>(xfb + (size_t)ii * Cn);

        float s = 0.f, comp = 0.f;
#pragma unroll
        for (int c4 = 0; c4 < Cn / 4; c4++) {
            float4 f = xs[c4];
            float kk[4] = {f.x, f.y, f.z, f.w};
#pragma unroll
            for (int u = 0; u < 4; u++) {
                float a = qv[4 * c4 + u], bb = kk[u];
                float p  = __fmul_rn(a, bb);
                float pe = fmaf(a, bb, -p);          // exact product tail
                float t  = __fadd_rn(s, p);          // TwoSum
                float z  = __fsub_rn(t, s);
                float se = __fadd_rn(__fsub_rn(s, __fsub_rn(t, z)),
                                     __fsub_rn(p, z));
                s = t;
                comp = __fadd_rn(comp, __fadd_rn(pe, se));
            }
        }
        double dot = (double)s + (double)comp;
        double sim = fmin(fmax(dot * rq * rinvb[ii], -1.0), 1.0);

        // insert into running top-9: (value desc, index asc)
        if (sim > bv[Kn - 1] || (sim == bv[Kn - 1] && ii < bi[Kn - 1])) {
            bv[Kn - 1] = sim; bi[Kn - 1] = ii;
#pragma unroll
            for (int pp = Kn - 1; pp > 0; --pp) {
                bool sw = (bv[pp] > bv[pp - 1]) ||
                          (bv[pp] == bv[pp - 1] && bi[pp] < bi[pp - 1]);
                if (sw) {
                    double tv = bv[pp]; bv[pp] = bv[pp - 1]; bv[pp - 1] = tv;
                    int    ti = bi[pp]; bi[pp] = bi[pp - 1]; bi[pp - 1] = ti;
                }
            }
        }
    }

    size_t obase = (size_t)qg * Kn;
#pragma unroll
    for (int p = 0; p < Kn; p++) {
        g_vals[obase + p] = (float)bv[p];
        g_idx[obase + p]  = bi[p];
    }
}

// ---------------------------------------------------------------------------
// Kernel 4: gather + conv. Warp handles 4 tokens; weight read once per
// (c,k) from L1-resident transposed global, reused across the 4 tokens.
// ---------------------------------------------------------------------------
__global__ __launch_bounds__(256) void conv_kernel(const float* __restrict__ bias,
                                                   float* __restrict__ out) {
    __shared__ float prime[8][4][Kn][Cn];

    int b = blockIdx.y;
    int warp = threadIdx.x >> 5;
    int lane = threadIdx.x & 31;
    const float* xfb = g_xf + (size_t)b * Tn * Cn;

    int t0 = blockIdx.x * 32 + warp * 4;
    size_t vbase = ((size_t)b * Tn + t0) * Kn;

#pragma unroll
    for (int m = 0; m < 4 * Kn; m++) {
        int tt = m / Kn, k = m % Kn;
        float vk = g_vals[vbase + tt * Kn + k];
        int   ik = g_idx[vbase + tt * Kn + k];
        prime[warp][tt][k][lane] = vk * xfb[(size_t)ik * Cn + lane];
    }
    __syncwarp();

    float bsl = bias[lane];
    float a0 = bsl, a1 = bsl, a2 = bsl, a3 = bsl;
#pragma unroll
    for (int c = 0; c < Cn; c++) {
#pragma unroll
        for (int k = 0; k < Kn; k++) {
            float wv = g_wT[(c * Kn + k) * COn + lane];
            a0 = fmaf(prime[warp][0][k][c], wv, a0);
            a1 = fmaf(prime[warp][1][k][c], wv, a1);
            a2 = fmaf(prime[warp][2][k][c], wv, a2);
            a3 = fmaf(prime[warp][3][k][c], wv, a3);
        }
    }
    size_t ob = ((size_t)b * COn + lane) * Tn + t0;
    out[ob + 0] = a0; out[ob + 1] = a1; out[ob + 2] = a2; out[ob + 3] = a3;
}

// ---------------------------------------------------------------------------
extern "C" void kernel_launch(void* const* d_in, const int* in_sizes, int n_in,
                              void* d_out, int out_size) {
    const float* x    = (const float*)d_in[0];  // [8,32,64,64]
    const float* w    = (const float*)d_in[1];  // [32,32,9]
    const float* bias = (const float*)d_in[2];  // [32]
    float* out = (float*)d_out;                 // [8,32,64,64]

    prep_kernel<<<dim3(Tn / 256, Bn), 256>>>(x);
    wt_kernel<<<(COn * Cn * Kn + 255) / 256, 256>>>(w);
    topk_kernel<<<dim3((Tn / QBLK) * NH, Bn), 256>>>();
    rescore_kernel<<<(Bn * Tn) / 128, 128>>>();
    conv_kernel<<<dim3(Tn / 32, Bn), 256>>>(bias, out);
}

// round 7
// speedup vs baseline: 1.3310x; 1.0481x over previous
#include <cuda_runtime.h>
#include <math.h>

// Problem constants (fixed shapes)
#define Bn  8
#define Cn  32
#define Tn  4096
#define Kn  9
#define COn 32
#define McL 10     // per-thread local candidates (fast pass)
#define MG  16     // merged candidates per query (exact-rescored)

// Scratch (no allocations allowed in kernel_launch)
__device__ float  g_xn32[Bn * Tn * Cn];   // normalized f32, token-major
__device__ float  g_xf[Bn * Tn * Cn];     // raw features f32, token-major
__device__ double g_rinv[Bn * Tn];        // f64 1/norm per token
__device__ float  g_wT[Kn * Cn * COn];    // weight [k][c][o]
__device__ int    g_cand[Bn * Tn * MG];   // merged candidate indices
__device__ float  g_vals[Bn * Tn * Kn];   // final top-K vals (sorted desc)
__device__ int    g_idx[Bn * Tn * Kn];    // final top-K indices

__device__ __forceinline__ unsigned f2tf32(float f) {
    unsigned r;
    asm("cvt.rna.tf32.f32 %0, %1;" : "=r"(r) : "f"(f));
    return r;
}

// ---------------------------------------------------------------------------
// Kernel 1: per-token transpose + f64 norm reciprocal + f32 normalized copy.
// ---------------------------------------------------------------------------
__global__ __launch_bounds__(256) void prep_kernel(const float* __restrict__ x) {
    int b = blockIdx.y;
    int t = blockIdx.x * 256 + threadIdx.x;
    const float* xb = x + (size_t)b * Cn * Tn;

    float v[Cn];
    double ss = 0.0;
#pragma unroll
    for (int c = 0; c < Cn; c++) {
        float f = xb[(size_t)c * Tn + t];
        v[c] = f;
        ss = fma((double)f, (double)f, ss);
    }
    double rin = 1.0 / fmax(sqrt(ss), 1e-12);
    g_rinv[(size_t)b * Tn + t] = rin;

    size_t base = ((size_t)b * Tn + t) * Cn;
    float4* pf = reinterpret_cast<float4*>(g_xf + base);
    float4* pn = reinterpret_cast<float4*>(g_xn32 + base);
#pragma unroll
    for (int c = 0; c < Cn; c += 4) {
        pf[c / 4] = make_float4(v[c], v[c + 1], v[c + 2], v[c + 3]);
        pn[c / 4] = make_float4((float)((double)v[c] * rin),
                                (float)((double)v[c + 1] * rin),
                                (float)((double)v[c + 2] * rin),
                                (float)((double)v[c + 3] * rin));
    }
}

// ---------------------------------------------------------------------------
// Kernel 1b: weight to [k][c][o] layout.
// ---------------------------------------------------------------------------
__global__ void wt_kernel(const float* __restrict__ w) {
    int i = blockIdx.x * 256 + threadIdx.x;
    if (i < COn * Cn * Kn) {
        int o = i / (Cn * Kn);
        int rem = i % (Cn * Kn);
        int c = rem / Kn;
        int k = rem % Kn;
        g_wT[(k * Cn + c) * COn + o] = w[i];
    }
}

// ---------------------------------------------------------------------------
// Kernel 2: tf32 tensor-core similarity fast pass -> 16 candidates/query.
// Block = 64 queries (4 warps x m16), sweeps 4096 keys in 128-key tiles.
// Keys staged tf32-converted in smem [ks*4+tig][key] float2 (stride 132 ->
// conflict-free LDS.64 B loads). m16n8k8 fragment map partitions the 8 keys
// of each n-tile across tig (cols 2*tig, 2*tig+1), so each query's keys are
// covered by 4 threads; per-thread local top-10 provably contains the true
// top-9 members of that thread's partition (tf32 noise ~1e-4 << local
// spacing ~1e-2). Block-end merge -> noisy global top-16 -> exact rescore.
// ---------------------------------------------------------------------------
#define KT 128   // keys per tile
#define QB 64    // queries per block

#define INSERT(lv, li, sval, sidx)                                           \
    if ((sval) > lv[McL - 1]) {                                              \
        lv[McL - 1] = (sval); li[McL - 1] = (sidx);                          \
        _Pragma("unroll")                                                    \
        for (int pp = McL - 1; pp > 0; --pp) {                               \
            if (lv[pp] > lv[pp - 1]) {                                       \
                float tv = lv[pp]; lv[pp] = lv[pp - 1]; lv[pp - 1] = tv;     \
                int ti = li[pp]; li[pp] = li[pp - 1]; li[pp - 1] = ti;       \
            }                                                                \
        }                                                                    \
    }

__global__ __launch_bounds__(128) void topk_kernel() {
    __shared__ uint2 kp[16][132];            // tf32 keys, pair (c, c+4)
    __shared__ float mv[QB][4 * McL + 1];    // pooled lists (+1 pad: bank-free)
    __shared__ int   mi[QB][4 * McL + 1];

    int b = blockIdx.y;
    int qbase = blockIdx.x * QB;
    int tid = threadIdx.x;
    int w = tid >> 5, lane = tid & 31;
    int gid = lane >> 2, tig = lane & 3;
    const float* xnb = g_xn32 + (size_t)b * Tn * Cn;

    int q0 = qbase + w * 16 + gid;   // fragment row gid
    int q1 = q0 + 8;                 // fragment row gid+8

    // A fragments (4 k-steps), tf32
    unsigned a[4][4];
#pragma unroll
    for (int ks = 0; ks < 4; ks++) {
        a[ks][0] = f2tf32(xnb[(size_t)q0 * Cn + ks * 8 + tig]);
        a[ks][1] = f2tf32(xnb[(size_t)q1 * Cn + ks * 8 + tig]);
        a[ks][2] = f2tf32(xnb[(size_t)q0 * Cn + ks * 8 + tig + 4]);
        a[ks][3] = f2tf32(xnb[(size_t)q1 * Cn + ks * 8 + tig + 4]);
    }

    float v0[McL], v1[McL];
    int   i0[McL], i1[McL];
#pragma unroll
    for (int p = 0; p < McL; p++) { v0[p] = -2.f; i0[p] = 0; v1[p] = -2.f; i1[p] = 0; }

    for (int tile = 0; tile < Tn; tile += KT) {
        __syncthreads();
        // stage + transpose + tf32-convert keys
        for (int i = tid; i < KT * 8; i += 128) {
            int key = i >> 3, c4 = i & 7;
            float4 f = *reinterpret_cast<const float4*>(
                xnb + (size_t)(tile + key) * Cn + c4 * 4);
            int ks = c4 >> 1, slot = c4 & 1;
            ((unsigned*)&kp[ks * 4 + 0][key])[slot] = f2tf32(f.x);
            ((unsigned*)&kp[ks * 4 + 1][key])[slot] = f2tf32(f.y);
            ((unsigned*)&kp[ks * 4 + 2][key])[slot] = f2tf32(f.z);
            ((unsigned*)&kp[ks * 4 + 3][key])[slot] = f2tf32(f.w);
        }
        __syncthreads();

#pragma unroll
        for (int nt = 0; nt < KT / 8; nt++) {
            float d0 = 0.f, d1 = 0.f, d2 = 0.f, d3 = 0.f;
#pragma unroll
            for (int ks = 0; ks < 4; ks++) {
                uint2 bb = kp[ks * 4 + tig][nt * 8 + gid];
                asm("mma.sync.aligned.m16n8k8.row.col.f32.tf32.tf32.f32 "
                    "{%0,%1,%2,%3}, {%4,%5,%6,%7}, {%8,%9}, {%0,%1,%2,%3};"
                    : "+f"(d0), "+f"(d1), "+f"(d2), "+f"(d3)
                    : "r"(a[ks][0]), "r"(a[ks][1]), "r"(a[ks][2]), "r"(a[ks][3]),
                      "r"(bb.x), "r"(bb.y));
            }
            int k0 = tile + nt * 8 + 2 * tig;
            INSERT(v0, i0, d0, k0)
            INSERT(v0, i0, d1, k0 + 1)
            INSERT(v1, i1, d2, k0)
            INSERT(v1, i1, d3, k0 + 1)
        }
    }

    // dump per-thread lists to pool
    int ql0 = w * 16 + gid, ql1 = ql0 + 8;
#pragma unroll
    for (int p = 0; p < McL; p++) {
        mv[ql0][tig * McL + p] = v0[p];  mi[ql0][tig * McL + p] = i0[p];
        mv[ql1][tig * McL + p] = v1[p];  mi[ql1][tig * McL + p] = i1[p];
    }
    __syncthreads();

    // merge: noisy top-16 of the 40-entry pool (ties -> lower index)
    if (tid < QB) {
        float bv[MG];
        int   bi[MG];
#pragma unroll
        for (int p = 0; p < MG; p++) { bv[p] = -3.f; bi[p] = 0x7fffffff; }
#pragma unroll 1
        for (int e = 0; e < 4 * McL; e++) {
            float s = mv[tid][e];
            int  ii = mi[tid][e];
            if (s > bv[MG - 1] || (s == bv[MG - 1] && ii < bi[MG - 1])) {
                bv[MG - 1] = s; bi[MG - 1] = ii;
#pragma unroll
                for (int pp = MG - 1; pp > 0; --pp) {
                    bool sw = (bv[pp] > bv[pp - 1]) ||
                              (bv[pp] == bv[pp - 1] && bi[pp] < bi[pp - 1]);
                    if (sw) {
                        float tv = bv[pp]; bv[pp] = bv[pp - 1]; bv[pp - 1] = tv;
                        int   ti = bi[pp]; bi[pp] = bi[pp - 1]; bi[pp - 1] = ti;
                    }
                }
            }
        }
        size_t obase = ((size_t)b * Tn + qbase + tid) * MG;
#pragma unroll
        for (int p = 0; p < MG; p++) g_cand[obase + p] = bi[p];
    }
}

// ---------------------------------------------------------------------------
// Kernel 3: rank-exact rescore of the 16 candidates (compensated fp32 Dot2
// + f64 norm reciprocals); running top-9 with (value desc, index asc).
// ---------------------------------------------------------------------------
__global__ __launch_bounds__(128) void rescore_kernel() {
    int qg = blockIdx.x * 128 + threadIdx.x;
    int b = qg >> 12;
    int q = qg & (Tn - 1);
    const float* xfb = g_xf + (size_t)b * Tn * Cn;
    const double* rinvb = g_rinv + (size_t)b * Tn;

    float qv[Cn];
    {
        const float4* qp = reinterpret_cast<const float4*>(xfb + (size_t)q * Cn);
#pragma unroll
        for (int c4 = 0; c4 < Cn / 4; c4++) {
            float4 f = qp[c4];
            qv[4 * c4] = f.x; qv[4 * c4 + 1] = f.y;
            qv[4 * c4 + 2] = f.z; qv[4 * c4 + 3] = f.w;
        }
    }
    double rq = rinvb[q];

    double bv[Kn];
    int    bi[Kn];
#pragma unroll
    for (int p = 0; p < Kn; p++) { bv[p] = -3.0; bi[p] = 0x7fffffff; }

    size_t cbase = (size_t)qg * MG;
#pragma unroll 1
    for (int m = 0; m < MG; m++) {
        int ii = g_cand[cbase + m];
        const float4* xs = reinterpret_cast<const float4*>(xfb + (size_t)ii * Cn);

        float s = 0.f, comp = 0.f;
#pragma unroll
        for (int c4 = 0; c4 < Cn / 4; c4++) {
            float4 f = xs[c4];
            float kk[4] = {f.x, f.y, f.z, f.w};
#pragma unroll
            for (int u = 0; u < 4; u++) {
                float aa = qv[4 * c4 + u], bb = kk[u];
                float p  = __fmul_rn(aa, bb);
                float pe = fmaf(aa, bb, -p);
                float t  = __fadd_rn(s, p);
                float z  = __fsub_rn(t, s);
                float se = __fadd_rn(__fsub_rn(s, __fsub_rn(t, z)),
                                     __fsub_rn(p, z));
                s = t;
                comp = __fadd_rn(comp, __fadd_rn(pe, se));
            }
        }
        double dot = (double)s + (double)comp;
        double sim = fmin(fmax(dot * rq * rinvb[ii], -1.0), 1.0);

        if (sim > bv[Kn - 1] || (sim == bv[Kn - 1] && ii < bi[Kn - 1])) {
            bv[Kn - 1] = sim; bi[Kn - 1] = ii;
#pragma unroll
            for (int pp = Kn - 1; pp > 0; --pp) {
                bool sw = (bv[pp] > bv[pp - 1]) ||
                          (bv[pp] == bv[pp - 1] && bi[pp] < bi[pp - 1]);
                if (sw) {
                    double tv = bv[pp]; bv[pp] = bv[pp - 1]; bv[pp - 1] = tv;
                    int    ti = bi[pp]; bi[pp] = bi[pp - 1]; bi[pp - 1] = ti;
                }
            }
        }
    }

    size_t obase = (size_t)qg * Kn;
#pragma unroll
    for (int p = 0; p < Kn; p++) {
        g_vals[obase + p] = (float)bv[p];
        g_idx[obase + p]  = bi[p];
    }
}

// ---------------------------------------------------------------------------
// Kernel 4: gather + conv. Warp = 4 tokens; per (k,c4): 4 coalesced weight
// LDG (L1-resident) + 4 broadcast LDS.128 prime loads + 16 FFMA.
// ---------------------------------------------------------------------------
__global__ __launch_bounds__(256) void conv_kernel(const float* __restrict__ bias,
                                                   float* __restrict__ out) {
    __shared__ float prime[8][4][Kn][Cn];

    int b = blockIdx.y;
    int warp = threadIdx.x >> 5;
    int lane = threadIdx.x & 31;
    const float* xfb = g_xf + (size_t)b * Tn * Cn;

    int t0 = blockIdx.x * 32 + warp * 4;
    size_t vbase = ((size_t)b * Tn + t0) * Kn;

#pragma unroll
    for (int m = 0; m < 4 * Kn; m++) {
        int tt = m / Kn, k = m % Kn;
        float vk = g_vals[vbase + tt * Kn + k];
        int   ik = g_idx[vbase + tt * Kn + k];
        prime[warp][tt][k][lane] = vk * xfb[(size_t)ik * Cn + lane];
    }
    __syncwarp();

    float bsl = bias[lane];
    float a0 = bsl, a1 = bsl, a2 = bsl, a3 = bsl;
#pragma unroll
    for (int k = 0; k < Kn; k++) {
#pragma unroll
        for (int c4 = 0; c4 < Cn / 4; c4++) {
            const float* wp = g_wT + (k * Cn + c4 * 4) * COn + lane;
            float w0 = wp[0];
            float w1 = wp[COn];
            float w2 = wp[2 * COn];
            float w3 = wp[3 * COn];
            float4 p0 = *reinterpret_cast<float4*>(&prime[warp][0][k][c4 * 4]);
            float4 p1 = *reinterpret_cast<float4*>(&prime[warp][1][k][c4 * 4]);
            float4 p2 = *reinterpret_cast<float4*>(&prime[warp][2][k][c4 * 4]);
            float4 p3 = *reinterpret_cast<float4*>(&prime[warp][3][k][c4 * 4]);
            a0 = fmaf(p0.x, w0, a0); a0 = fmaf(p0.y, w1, a0);
            a0 = fmaf(p0.z, w2, a0); a0 = fmaf(p0.w, w3, a0);
            a1 = fmaf(p1.x, w0, a1); a1 = fmaf(p1.y, w1, a1);
            a1 = fmaf(p1.z, w2, a1); a1 = fmaf(p1.w, w3, a1);
            a2 = fmaf(p2.x, w0, a2); a2 = fmaf(p2.y, w1, a2);
            a2 = fmaf(p2.z, w2, a2); a2 = fmaf(p2.w, w3, a2);
            a3 = fmaf(p3.x, w0, a3); a3 = fmaf(p3.y, w1, a3);
            a3 = fmaf(p3.z, w2, a3); a3 = fmaf(p3.w, w3, a3);
        }
    }
    size_t ob = ((size_t)b * COn + lane) * Tn + t0;
    out[ob + 0] = a0; out[ob + 1] = a1; out[ob + 2] = a2; out[ob + 3] = a3;
}

// ---------------------------------------------------------------------------
extern "C" void kernel_launch(void* const* d_in, const int* in_sizes, int n_in,
                              void* d_out, int out_size) {
    const float* x    = (const float*)d_in[0];  // [8,32,64,64]
    const float* w    = (const float*)d_in[1];  // [32,32,9]
    const float* bias = (const float*)d_in[2];  // [32]
    float* out = (float*)d_out;                 // [8,32,64,64]

    prep_kernel<<<dim3(Tn / 256, Bn), 256>>>(x);
    wt_kernel<<<(COn * Cn * Kn + 255) / 256, 256>>>(w);
    topk_kernel<<<dim3(Tn / QB, Bn), 128>>>();
    rescore_kernel<<<(Bn * Tn) / 128, 128>>>();
    conv_kernel<<<dim3(Tn / 32, Bn), 256>>>(bias, out);
}

// round 8
// speedup vs baseline: 2.2711x; 1.7064x over previous
#include <cuda_runtime.h>
#include <math.h>

// Problem constants (fixed shapes)
#define Bn  8
#define Cn  32
#define Tn  4096
#define Kn  9
#define COn 32
#define CAP 64     // candidate buffer capacity per query

// Scratch (no allocations allowed in kernel_launch)
__device__ float  g_xn32[Bn * Tn * Cn];   // normalized f32, token-major
__device__ float  g_xf[Bn * Tn * Cn];     // raw features f32, token-major
__device__ double g_rinv[Bn * Tn];        // f64 1/norm per token
__device__ float  g_wT[Kn * Cn * COn];    // weight [k][c][o]
__device__ int    g_cnt[Bn * Tn];         // candidate count per query
__device__ int    g_cand[Bn * Tn * CAP];  // candidate indices
__device__ float  g_vals[Bn * Tn * Kn];   // final top-K vals (sorted desc)
__device__ int    g_idx[Bn * Tn * Kn];    // final top-K indices

__device__ __forceinline__ unsigned f2tf32(float f) {
    unsigned r;
    asm("cvt.rna.tf32.f32 %0, %1;" : "=r"(r) : "f"(f));
    return r;
}

// ---------------------------------------------------------------------------
// Kernel 1: per-token transpose + f64 norm reciprocal + f32 normalized copy.
// ---------------------------------------------------------------------------
__global__ __launch_bounds__(256) void prep_kernel(const float* __restrict__ x) {
    int b = blockIdx.y;
    int t = blockIdx.x * 256 + threadIdx.x;
    const float* xb = x + (size_t)b * Cn * Tn;

    float v[Cn];
    double ss = 0.0;
#pragma unroll
    for (int c = 0; c < Cn; c++) {
        float f = xb[(size_t)c * Tn + t];
        v[c] = f;
        ss = fma((double)f, (double)f, ss);
    }
    double rin = 1.0 / fmax(sqrt(ss), 1e-12);
    g_rinv[(size_t)b * Tn + t] = rin;

    size_t base = ((size_t)b * Tn + t) * Cn;
    float4* pf = reinterpret_cast<float4*>(g_xf + base);
    float4* pn = reinterpret_cast<float4*>(g_xn32 + base);
#pragma unroll
    for (int c = 0; c < Cn; c += 4) {
        pf[c / 4] = make_float4(v[c], v[c + 1], v[c + 2], v[c + 3]);
        pn[c / 4] = make_float4((float)((double)v[c] * rin),
                                (float)((double)v[c + 1] * rin),
                                (float)((double)v[c + 2] * rin),
                                (float)((double)v[c + 3] * rin));
    }
}

// ---------------------------------------------------------------------------
// Kernel 1b: weight to [k][c][o] layout.
// ---------------------------------------------------------------------------
__global__ void wt_kernel(const float* __restrict__ w) {
    int i = blockIdx.x * 256 + threadIdx.x;
    if (i < COn * Cn * Kn) {
        int o = i / (Cn * Kn);
        int rem = i % (Cn * Kn);
        int c = rem / Kn;
        int k = rem % Kn;
        g_wT[(k * Cn + c) * COn + o] = w[i];
    }
}

// ---------------------------------------------------------------------------
// Kernel 2: tf32 MMA similarity, threshold-then-collect selection.
// Block = 64 queries (4 warps x m16). Sweep 1 (phase A): per-thread
// VALUE-ONLY top-3 of its 1024-key partition; merged 12 values per query
// give tau = 9th-largest of a subset <= global 9th-largest. Sweep 2
// (phase B): identical sims recomputed; sim >= tau-EPS appends its index
// to a smem buffer (no sorted inserts anywhere). Exact rescore downstream
// recovers the true top-9 + ordering.
// ---------------------------------------------------------------------------
#define KT 128   // keys per tile
#define QB 64    // queries per block
#define EPS 4e-3f

__global__ __launch_bounds__(128) void topk_kernel() {
    __shared__ uint2 kp[16][133];         // tf32 keys; stride 133 -> STS conflict-free
    __shared__ float mv[QB][13];          // 12 merged values + pad
    __shared__ float tau_s[QB];
    __shared__ int   cnt_s[QB];
    __shared__ int   buf[QB][CAP];

    int b = blockIdx.y;
    int qbase = blockIdx.x * QB;
    int tid = threadIdx.x;
    int w = tid >> 5, lane = tid & 31;
    int gid = lane >> 2, tig = lane & 3;
    const float* xnb = g_xn32 + (size_t)b * Tn * Cn;

    int q0 = qbase + w * 16 + gid;   // fragment row gid
    int q1 = q0 + 8;                 // fragment row gid+8

    // A fragments (4 k-steps), tf32
    unsigned a[4][4];
#pragma unroll
    for (int ks = 0; ks < 4; ks++) {
        a[ks][0] = f2tf32(xnb[(size_t)q0 * Cn + ks * 8 + tig]);
        a[ks][1] = f2tf32(xnb[(size_t)q1 * Cn + ks * 8 + tig]);
        a[ks][2] = f2tf32(xnb[(size_t)q0 * Cn + ks * 8 + tig + 4]);
        a[ks][3] = f2tf32(xnb[(size_t)q1 * Cn + ks * 8 + tig + 4]);
    }

    // ---------------- Phase A: value-only top-3 per thread ----------------
    float v0[3] = {-2.f, -2.f, -2.f};
    float v1[3] = {-2.f, -2.f, -2.f};

#define TOP3(vv, s)                                                          \
    if ((s) > vv[2]) {                                                       \
        vv[2] = (s);                                                         \
        if (vv[2] > vv[1]) { float tt = vv[2]; vv[2] = vv[1]; vv[1] = tt; }  \
        if (vv[1] > vv[0]) { float tt = vv[1]; vv[1] = vv[0]; vv[0] = tt; }  \
    }

    for (int tile = 0; tile < Tn; tile += KT) {
        __syncthreads();
        for (int i = tid; i < KT * 8; i += 128) {
            int key = i >> 3, c4 = i & 7;
            float4 f = *reinterpret_cast<const float4*>(
                xnb + (size_t)(tile + key) * Cn + c4 * 4);
            int ks = c4 >> 1, slot = c4 & 1;
            ((unsigned*)&kp[ks * 4 + 0][key])[slot] = f2tf32(f.x);
            ((unsigned*)&kp[ks * 4 + 1][key])[slot] = f2tf32(f.y);
            ((unsigned*)&kp[ks * 4 + 2][key])[slot] = f2tf32(f.z);
            ((unsigned*)&kp[ks * 4 + 3][key])[slot] = f2tf32(f.w);
        }
        __syncthreads();

#pragma unroll
        for (int nt = 0; nt < KT / 8; nt++) {
            float d0 = 0.f, d1 = 0.f, d2 = 0.f, d3 = 0.f;
#pragma unroll
            for (int ks = 0; ks < 4; ks++) {
                uint2 bb = kp[ks * 4 + tig][nt * 8 + gid];
                asm("mma.sync.aligned.m16n8k8.row.col.f32.tf32.tf32.f32 "
                    "{%0,%1,%2,%3}, {%4,%5,%6,%7}, {%8,%9}, {%0,%1,%2,%3};"
                    : "+f"(d0), "+f"(d1), "+f"(d2), "+f"(d3)
                    : "r"(a[ks][0]), "r"(a[ks][1]), "r"(a[ks][2]), "r"(a[ks][3]),
                      "r"(bb.x), "r"(bb.y));
            }
            TOP3(v0, d0)
            TOP3(v0, d1)
            TOP3(v1, d2)
            TOP3(v1, d3)
        }
    }

    // merge 4x3 values per query -> tau
    int ql0 = w * 16 + gid, ql1 = ql0 + 8;
#pragma unroll
    for (int p = 0; p < 3; p++) {
        mv[ql0][tig * 3 + p] = v0[p];
        mv[ql1][tig * 3 + p] = v1[p];
    }
    __syncthreads();

    if (tid < QB) {
        float bv[Kn];
#pragma unroll
        for (int p = 0; p < Kn; p++) bv[p] = -3.f;
#pragma unroll
        for (int e = 0; e < 12; e++) {
            float s = mv[tid][e];
            if (s > bv[Kn - 1]) {
                bv[Kn - 1] = s;
#pragma unroll
                for (int pp = Kn - 1; pp > 0; --pp) {
                    if (bv[pp] > bv[pp - 1]) {
                        float tt = bv[pp]; bv[pp] = bv[pp - 1]; bv[pp - 1] = tt;
                    }
                }
            }
        }
        tau_s[tid] = bv[Kn - 1] - EPS;
        cnt_s[tid] = 0;
    }
    __syncthreads();

    float t0 = tau_s[ql0];
    float t1 = tau_s[ql1];

    // ---------------- Phase B: collect indices with sim >= tau ------------
    for (int tile = 0; tile < Tn; tile += KT) {
        __syncthreads();
        for (int i = tid; i < KT * 8; i += 128) {
            int key = i >> 3, c4 = i & 7;
            float4 f = *reinterpret_cast<const float4*>(
                xnb + (size_t)(tile + key) * Cn + c4 * 4);
            int ks = c4 >> 1, slot = c4 & 1;
            ((unsigned*)&kp[ks * 4 + 0][key])[slot] = f2tf32(f.x);
            ((unsigned*)&kp[ks * 4 + 1][key])[slot] = f2tf32(f.y);
            ((unsigned*)&kp[ks * 4 + 2][key])[slot] = f2tf32(f.z);
            ((unsigned*)&kp[ks * 4 + 3][key])[slot] = f2tf32(f.w);
        }
        __syncthreads();

#pragma unroll
        for (int nt = 0; nt < KT / 8; nt++) {
            float d0 = 0.f, d1 = 0.f, d2 = 0.f, d3 = 0.f;
#pragma unroll
            for (int ks = 0; ks < 4; ks++) {
                uint2 bb = kp[ks * 4 + tig][nt * 8 + gid];
                asm("mma.sync.aligned.m16n8k8.row.col.f32.tf32.tf32.f32 "
                    "{%0,%1,%2,%3}, {%4,%5,%6,%7}, {%8,%9}, {%0,%1,%2,%3};"
                    : "+f"(d0), "+f"(d1), "+f"(d2), "+f"(d3)
                    : "r"(a[ks][0]), "r"(a[ks][1]), "r"(a[ks][2]), "r"(a[ks][3]),
                      "r"(bb.x), "r"(bb.y));
            }
            int k0 = tile + nt * 8 + 2 * tig;
            if (d0 >= t0) { int p = atomicAdd(&cnt_s[ql0], 1); if (p < CAP) buf[ql0][p] = k0; }
            if (d1 >= t0) { int p = atomicAdd(&cnt_s[ql0], 1); if (p < CAP) buf[ql0][p] = k0 + 1; }
            if (d2 >= t1) { int p = atomicAdd(&cnt_s[ql1], 1); if (p < CAP) buf[ql1][p] = k0; }
            if (d3 >= t1) { int p = atomicAdd(&cnt_s[ql1], 1); if (p < CAP) buf[ql1][p] = k0 + 1; }
        }
    }
    __syncthreads();

    // write out buffers + counts
    for (int i = tid; i < QB * CAP; i += 128) {
        int ql = i >> 6, j = i & (CAP - 1);
        g_cand[((size_t)b * Tn + qbase + ql) * CAP + j] = buf[ql][j];
    }
    if (tid < QB) {
        int c = cnt_s[tid];
        g_cnt[(size_t)b * Tn + qbase + tid] = (c < CAP) ? c : CAP;
    }
}

// ---------------------------------------------------------------------------
// Kernel 3: rank-exact rescore of collected candidates (compensated fp32
// Dot2 + f64 norm reciprocals); running top-9, (value desc, index asc).
// ---------------------------------------------------------------------------
__global__ __launch_bounds__(128) void rescore_kernel() {
    int qg = blockIdx.x * 128 + threadIdx.x;
    int b = qg >> 12;
    int q = qg & (Tn - 1);
    const float* xfb = g_xf + (size_t)b * Tn * Cn;
    const double* rinvb = g_rinv + (size_t)b * Tn;

    float qv[Cn];
    {
        const float4* qp = reinterpret_cast<const float4*>(xfb + (size_t)q * Cn);
#pragma unroll
        for (int c4 = 0; c4 < Cn / 4; c4++) {
            float4 f = qp[c4];
            qv[4 * c4] = f.x; qv[4 * c4 + 1] = f.y;
            qv[4 * c4 + 2] = f.z; qv[4 * c4 + 3] = f.w;
        }
    }
    double rq = rinvb[q];

    double bv[Kn];
    int    bi[Kn];
#pragma unroll
    for (int p = 0; p < Kn; p++) { bv[p] = -3.0; bi[p] = 0x7fffffff; }

    int cnt = g_cnt[qg];
    size_t cbase = (size_t)qg * CAP;
#pragma unroll 1
    for (int m = 0; m < cnt; m++) {
        int ii = g_cand[cbase + m];
        const float4* xs = reinterpret_cast<const float4*>(xfb + (size_t)ii * Cn);

        float s = 0.f, comp = 0.f;
#pragma unroll
        for (int c4 = 0; c4 < Cn / 4; c4++) {
            float4 f = xs[c4];
            float kk[4] = {f.x, f.y, f.z, f.w};
#pragma unroll
            for (int u = 0; u < 4; u++) {
                float aa = qv[4 * c4 + u], bb = kk[u];
                float p  = __fmul_rn(aa, bb);
                float pe = fmaf(aa, bb, -p);
                float t  = __fadd_rn(s, p);
                float z  = __fsub_rn(t, s);
                float se = __fadd_rn(__fsub_rn(s, __fsub_rn(t, z)),
                                     __fsub_rn(p, z));
                s = t;
                comp = __fadd_rn(comp, __fadd_rn(pe, se));
            }
        }
        double dot = (double)s + (double)comp;
        double sim = fmin(fmax(dot * rq * rinvb[ii], -1.0), 1.0);

        if (sim > bv[Kn - 1] || (sim == bv[Kn - 1] && ii < bi[Kn - 1])) {
            bv[Kn - 1] = sim; bi[Kn - 1] = ii;
#pragma unroll
            for (int pp = Kn - 1; pp > 0; --pp) {
                bool sw = (bv[pp] > bv[pp - 1]) ||
                          (bv[pp] == bv[pp - 1] && bi[pp] < bi[pp - 1]);
                if (sw) {
                    double tv = bv[pp]; bv[pp] = bv[pp - 1]; bv[pp - 1] = tv;
                    int    ti = bi[pp]; bi[pp] = bi[pp - 1]; bi[pp - 1] = ti;
                }
            }
        }
    }

    size_t obase = (size_t)qg * Kn;
#pragma unroll
    for (int p = 0; p < Kn; p++) {
        g_vals[obase + p] = (float)bv[p];
        g_idx[obase + p]  = bi[p];
    }
}

// ---------------------------------------------------------------------------
// Kernel 4: gather + conv. Warp = 4 tokens; per (k,c4): 4 coalesced weight
// LDG (L1-resident) + 4 broadcast LDS.128 prime loads + 16 FFMA.
// ---------------------------------------------------------------------------
__global__ __launch_bounds__(256) void conv_kernel(const float* __restrict__ bias,
                                                   float* __restrict__ out) {
    __shared__ float prime[8][4][Kn][Cn];

    int b = blockIdx.y;
    int warp = threadIdx.x >> 5;
    int lane = threadIdx.x & 31;
    const float* xfb = g_xf + (size_t)b * Tn * Cn;

    int t0 = blockIdx.x * 32 + warp * 4;
    size_t vbase = ((size_t)b * Tn + t0) * Kn;

#pragma unroll
    for (int m = 0; m < 4 * Kn; m++) {
        int tt = m / Kn, k = m % Kn;
        float vk = g_vals[vbase + tt * Kn + k];
        int   ik = g_idx[vbase + tt * Kn + k];
        prime[warp][tt][k][lane] = vk * xfb[(size_t)ik * Cn + lane];
    }
    __syncwarp();

    float bsl = bias[lane];
    float a0 = bsl, a1 = bsl, a2 = bsl, a3 = bsl;
#pragma unroll
    for (int k = 0; k < Kn; k++) {
#pragma unroll
        for (int c4 = 0; c4 < Cn / 4; c4++) {
            const float* wp = g_wT + (k * Cn + c4 * 4) * COn + lane;
            float w0 = wp[0];
            float w1 = wp[COn];
            float w2 = wp[2 * COn];
            float w3 = wp[3 * COn];
            float4 p0 = *reinterpret_cast<float4*>(&prime[warp][0][k][c4 * 4]);
            float4 p1 = *reinterpret_cast<float4*>(&prime[warp][1][k][c4 * 4]);
            float4 p2 = *reinterpret_cast<float4*>(&prime[warp][2][k][c4 * 4]);
            float4 p3 = *reinterpret_cast<float4*>(&prime[warp][3][k][c4 * 4]);
            a0 = fmaf(p0.x, w0, a0); a0 = fmaf(p0.y, w1, a0);
            a0 = fmaf(p0.z, w2, a0); a0 = fmaf(p0.w, w3, a0);
            a1 = fmaf(p1.x, w0, a1); a1 = fmaf(p1.y, w1, a1);
            a1 = fmaf(p1.z, w2, a1); a1 = fmaf(p1.w, w3, a1);
            a2 = fmaf(p2.x, w0, a2); a2 = fmaf(p2.y, w1, a2);
            a2 = fmaf(p2.z, w2, a2); a2 = fmaf(p2.w, w3, a2);
            a3 = fmaf(p3.x, w0, a3); a3 = fmaf(p3.y, w1, a3);
            a3 = fmaf(p3.z, w2, a3); a3 = fmaf(p3.w, w3, a3);
        }
    }
    size_t ob = ((size_t)b * COn + lane) * Tn + t0;
    out[ob + 0] = a0; out[ob + 1] = a1; out[ob + 2] = a2; out[ob + 3] = a3;
}

// ---------------------------------------------------------------------------
extern "C" void kernel_launch(void* const* d_in, const int* in_sizes, int n_in,
                              void* d_out, int out_size) {
    const float* x    = (const float*)d_in[0];  // [8,32,64,64]
    const float* w    = (const float*)d_in[1];  // [32,32,9]
    const float* bias = (const float*)d_in[2];  // [32]
    float* out = (float*)d_out;                 // [8,32,64,64]

    prep_kernel<<<dim3(Tn / 256, Bn), 256>>>(x);
    wt_kernel<<<(COn * Cn * Kn + 255) / 256, 256>>>(w);
    topk_kernel<<<dim3(Tn / QB, Bn), 128>>>();
    rescore_kernel<<<(Bn * Tn) / 128, 128>>>();
    conv_kernel<<<dim3(Tn / 32, Bn), 256>>>(bias, out);
}